// round 16
// baseline (speedup 1.0000x reference)
#include <cuda_runtime.h>
#include <cuda_fp16.h>
#include <cstdint>

// Problem constants
#define BB 4
#define VV 256
#define HH 128
constexpr int ROWS_H = BB * VV;           // 1024
constexpr int ROWS_E = BB * VV * VV;      // 262144
constexpr int NBLK2  = ROWS_E / 128;      // 2048 stat row-blocks (128 rows each)
constexpr int GRID_MAIN = ROWS_E / 256;   // 1024 (one block per (b,i))
constexpr float EPS  = 1e-5f;

// ---------------- smem geometry for k_main ----------------
constexpr int LDC    = 72;                  // fp16 elems per tile row (144 B; 9 units, odd)
constexpr int TILE_B = 128 * LDC * 2;       // 18432 B per fp16 tile (128 rows x 64 cols)
constexpr int SM_C2  = 0;                   // 128 floats
constexpr int SM_AHI = 1024;
constexpr int SM_BW0 = SM_AHI + TILE_B;     // 19456
constexpr int SM_BW1 = SM_BW0 + TILE_B;     // 37888
constexpr int SM_RED = SM_BW1 + TILE_B;     // 56320 (3 x 512 floats)
constexpr int SM_TOTAL = SM_RED + 6144;     // 62464 -> 2 CTAs/SM easily

// Scratch
__device__ float g_enew[(size_t)ROWS_E * HH];   // 134 MB
__device__ float g_lin[4 * ROWS_H * HH];        // Uh,Vh,Ah,Bh
__device__ __align__(16) char g_bt[2 * TILE_B]; // pre-converted Cw fp16 [chunk]
__device__ float g_statS[HH * NBLK2];
__device__ float g_statQ[HH * NBLK2];
__device__ float g_aggp[HH * NBLK2];
__device__ float g_hnew[ROWS_H * HH];
__device__ float g_scaleE[HH];
__device__ float g_shiftE[HH];

__device__ __forceinline__ uint32_t smem_u32(const void* p) {
    uint32_t a;
    asm("{ .reg .u64 t; cvta.to.shared.u64 t, %1; cvt.u32.u64 %0, t; }" : "=r"(a) : "l"(p));
    return a;
}
__device__ __forceinline__ void ldmatrix_x4(uint32_t& r0, uint32_t& r1, uint32_t& r2, uint32_t& r3, uint32_t addr) {
    asm volatile("ldmatrix.sync.aligned.m8n8.x4.shared.b16 {%0,%1,%2,%3}, [%4];"
        : "=r"(r0), "=r"(r1), "=r"(r2), "=r"(r3) : "r"(addr) : "memory");
}
__device__ __forceinline__ void mma16816(float (&d)[4], const uint32_t (&a)[4], uint32_t b0, uint32_t b1) {
    asm("mma.sync.aligned.m16n8k16.row.col.f32.f16.f16.f32 "
        "{%0,%1,%2,%3}, {%4,%5,%6,%7}, {%8,%9}, {%0,%1,%2,%3};"
        : "+f"(d[0]), "+f"(d[1]), "+f"(d[2]), "+f"(d[3])
        : "r"(a[0]), "r"(a[1]), "r"(a[2]), "r"(a[3]), "r"(b0), "r"(b1));
}
__device__ __forceinline__ void cp_async16(uint32_t smem_dst, const void* gmem_src) {
    asm volatile("cp.async.cg.shared.global [%0], [%1], 16;" :: "r"(smem_dst), "l"(gmem_src) : "memory");
}
#define CP_COMMIT() asm volatile("cp.async.commit_group;" ::: "memory")
#define CP_WAIT(n)  asm volatile("cp.async.wait_group %0;" :: "n"(n) : "memory")

__device__ __forceinline__ void cvt_store4(float4 v, char* smem, uint32_t off) {
    __half h0 = __float2half_rn(v.x), h1 = __float2half_rn(v.y);
    __half h2 = __float2half_rn(v.z), h3 = __float2half_rn(v.w);
    uint2 u;
    u.x = ((uint32_t)__half_as_ushort(h1) << 16) | __half_as_ushort(h0);
    u.y = ((uint32_t)__half_as_ushort(h3) << 16) | __half_as_ushort(h2);
    *(uint2*)(smem + off) = u;
}

// ---------------- K1: HMMA Ce GEMM (fp16, TM=256 per block) ----------------
__global__ void __launch_bounds__(256, 2)
k_main(const float* __restrict__ e, const float* __restrict__ Cb) {
    extern __shared__ char sm[];
    uint32_t smb = smem_u32(sm);
    int tid = threadIdx.x;
    int wid = tid >> 5, lane = tid & 31;

    int blk = blockIdx.x;         // == bi = b*V + i
    int b   = blk >> 8;
    size_t rbase0 = (size_t)blk * 256;

    // c2 = Cb + Bh[bi]
    if (tid < HH)
        ((float*)(sm + SM_C2))[tid] = Cb[tid] + g_lin[(size_t)3 * ROWS_H * HH + (size_t)blk * HH + tid];

    // Both B chunk tiles, once per block
    for (int i = tid; i < 2 * TILE_B / 16; i += 256)
        cp_async16(smb + SM_BW0 + i * 16, g_bt + i * 16);
    CP_COMMIT();

    int wm = wid >> 1, wn = wid & 1;     // 4 x 2 warp grid, warp tile 32x64
    uint32_t aLaneOff = (uint32_t)(wm * 32 + (lane & 15)) * (LDC * 2) + (lane >> 4) * 16;
    uint32_t bLaneOff = (uint32_t)(wn * 64 + (((lane >> 4) & 1) * 8) + (lane & 7)) * (LDC * 2)
                      + ((lane >> 3) & 1) * 16;

#pragma unroll
    for (int t = 0; t < 2; t++) {
        size_t rbase = rbase0 + t * 128;
        float d[2][8][4];
#pragma unroll
        for (int mt = 0; mt < 2; mt++)
#pragma unroll
            for (int nt = 0; nt < 8; nt++)
#pragma unroll
                for (int q = 0; q < 4; q++) d[mt][nt][q] = 0.f;

#pragma unroll
        for (int ch = 0; ch < 2; ch++) {
            // load + convert A (128 rows x 64 K) — direct LDG
            const float* eb = e + rbase * HH + ch * 64;
            for (int idx = tid; idx < 128 * 16; idx += 256) {
                int row = idx >> 4, c4 = idx & 15;
                uint32_t off = (uint32_t)row * (LDC * 2) + c4 * 8;
                float4 ev = *(const float4*)&eb[(size_t)row * HH + c4 * 4];
                cvt_store4(ev, sm, SM_AHI + off);
            }
            if (t == 0 && ch == 0) { CP_WAIT(0); }
            __syncthreads();

            uint32_t aBase = smb + SM_AHI + aLaneOff;
            uint32_t bBase = smb + (ch ? SM_BW1 : SM_BW0) + bLaneOff;
#pragma unroll
            for (int kk = 0; kk < 4; kk++) {
                uint32_t bb[16];
#pragma unroll
                for (int q = 0; q < 4; q++)
                    ldmatrix_x4(bb[q * 4], bb[q * 4 + 1], bb[q * 4 + 2], bb[q * 4 + 3],
                                bBase + kk * 32 + (uint32_t)q * 16 * (LDC * 2));
                uint32_t a0[4], a1[4];
                ldmatrix_x4(a0[0], a0[1], a0[2], a0[3], aBase + kk * 32);
                ldmatrix_x4(a1[0], a1[1], a1[2], a1[3], aBase + kk * 32 + 16 * (LDC * 2));
#pragma unroll
                for (int nt = 0; nt < 8; nt++) {
                    uint32_t b0 = bb[(nt >> 1) * 4 + (nt & 1) * 2];
                    uint32_t b1 = bb[(nt >> 1) * 4 + (nt & 1) * 2 + 1];
                    mma16816(d[0][nt], a0, b0, b1);
                    mma16816(d[1][nt], a1, b0, b1);
                }
            }
            __syncthreads();   // A tile consumed; next chunk may overwrite
        }

        // -------- fragment-direct epilogue for this tile --------
        {
            int g = lane >> 2, t2 = (lane & 3) * 2;
            const float* c2s = (const float*)(sm + SM_C2);
            const float* ahB = g_lin + (size_t)2 * ROWS_H * HH + (size_t)(b * VV + t * 128) * HH;
            const float* vhB = g_lin + (size_t)1 * ROWS_H * HH + (size_t)(b * VV + t * 128) * HH;
            float* enB = g_enew + rbase * HH;
            float* redS = (float*)(sm + SM_RED);
            float* redQ = redS + 512;
            float* redA = redQ + 512;

#pragma unroll
            for (int nt = 0; nt < 8; nt++) {
                int c = wn * 64 + nt * 8 + t2;
                float c2a = c2s[c], c2b = c2s[c + 1];
                float pS0 = 0.f, pS1 = 0.f, pQ0 = 0.f, pQ1 = 0.f, pA0 = 0.f, pA1 = 0.f;
#pragma unroll
                for (int mt = 0; mt < 2; mt++) {
#pragma unroll
                    for (int h = 0; h < 2; h++) {
                        int r = wm * 32 + mt * 16 + h * 8 + g;
                        float2 ahv = *(const float2*)&ahB[(size_t)r * HH + c];
                        float2 vhv = *(const float2*)&vhB[(size_t)r * HH + c];
                        float x0 = d[mt][nt][h * 2 + 0] + c2a + ahv.x;
                        float x1 = d[mt][nt][h * 2 + 1] + c2b + ahv.y;
                        *(float2*)&enB[(size_t)r * HH + c] = make_float2(x0, x1);
                        pS0 += x0; pS1 += x1;
                        pQ0 = fmaf(x0, x0, pQ0); pQ1 = fmaf(x1, x1, pQ1);
                        pA0 = fmaf(vhv.x, 1.f / (1.f + __expf(-x0)), pA0);
                        pA1 = fmaf(vhv.y, 1.f / (1.f + __expf(-x1)), pA1);
                    }
                }
#pragma unroll
                for (int m = 4; m <= 16; m <<= 1) {
                    pS0 += __shfl_xor_sync(0xffffffffu, pS0, m);
                    pS1 += __shfl_xor_sync(0xffffffffu, pS1, m);
                    pQ0 += __shfl_xor_sync(0xffffffffu, pQ0, m);
                    pQ1 += __shfl_xor_sync(0xffffffffu, pQ1, m);
                    pA0 += __shfl_xor_sync(0xffffffffu, pA0, m);
                    pA1 += __shfl_xor_sync(0xffffffffu, pA1, m);
                }
                if (g == 0) {
                    redS[wm * 128 + c] = pS0; redS[wm * 128 + c + 1] = pS1;
                    redQ[wm * 128 + c] = pQ0; redQ[wm * 128 + c + 1] = pQ1;
                    redA[wm * 128 + c] = pA0; redA[wm * 128 + c + 1] = pA1;
                }
            }
        }
        __syncthreads();
        if (tid < HH) {
            float* redS = (float*)(sm + SM_RED);
            float* redQ = redS + 512;
            float* redA = redQ + 512;
            float S = 0.f, Q = 0.f, A = 0.f;
#pragma unroll
            for (int w = 0; w < 4; w++) {
                S += redS[w * 128 + tid];
                Q += redQ[w * 128 + tid];
                A += redA[w * 128 + tid];
            }
            int rowblk = blk * 2 + t;
            g_statS[(size_t)tid * NBLK2 + rowblk] = S;
            g_statQ[(size_t)tid * NBLK2 + rowblk] = Q;
            g_aggp[(size_t)tid * NBLK2 + rowblk]  = A;
        }
        // red not rewritten until after ≥2 barriers in next tile's MMA phases — safe
    }
}

// ---------------- K0: four small linears + Cw pre-convert (y==4) ----------------
constexpr int WS_STRIDE = 132;
constexpr int SMEM_LIN = (HH * WS_STRIDE + 64 * HH) * 4;

__device__ __forceinline__ void fma2(unsigned long long& d, unsigned long long a, unsigned long long b) {
    asm("fma.rn.f32x2 %0, %1, %2, %0;" : "+l"(d) : "l"(a), "l"(b));
}
__device__ __forceinline__ float2 unpack2(unsigned long long v) {
    float2 r; asm("mov.b64 {%0,%1}, %2;" : "=f"(r.x), "=f"(r.y) : "l"(v)); return r;
}

__global__ void k_lin(const float* __restrict__ h,
                      const float* __restrict__ W0, const float* __restrict__ b0,
                      const float* __restrict__ W1, const float* __restrict__ b1,
                      const float* __restrict__ W2, const float* __restrict__ b2,
                      const float* __restrict__ W3, const float* __restrict__ b3,
                      const float* __restrict__ Cw) {
    if (blockIdx.y == 4) {
        int ch = blockIdx.x & 1;
        if (blockIdx.x >= 2) return;
        char* dst = g_bt + (size_t)ch * TILE_B;
        const float* wb = Cw + ch * 64;
        for (int idx = threadIdx.x; idx < 128 * 16; idx += 256) {
            int row = idx >> 4, c4 = idx & 15;
            uint32_t off = (uint32_t)row * (LDC * 2) + c4 * 8;
            float4 wv = *(const float4*)&wb[(size_t)row * HH + c4 * 4];
            cvt_store4(wv, dst, off);
        }
        return;
    }
    extern __shared__ float smf[];
    float* Ws = smf;
    float* As = Ws + HH * WS_STRIDE;

    int m = blockIdx.y;
    const float* W    = (m == 0) ? W0 : (m == 1) ? W1 : (m == 2) ? W2 : W3;
    const float* bias = (m == 0) ? b0 : (m == 1) ? b1 : (m == 2) ? b2 : b3;

    int tid = threadIdx.x;
    for (int i = tid; i < HH * 32; i += 256) {
        int n = i >> 5, kc = i & 31;
        *(float4*)&Ws[n * WS_STRIDE + kc * 4] = *(const float4*)&W[n * HH + kc * 4];
    }
    int r0 = blockIdx.x * 64;
    const float4* hsrc = (const float4*)(h + (size_t)r0 * HH);
    for (int i = tid; i < 64 * 32; i += 256) ((float4*)As)[i] = hsrc[i];
    __syncthreads();

    int tr = tid >> 5, tc = tid & 31;
    int jj0 = tr * 8;
    unsigned long long acc[8][4];
#pragma unroll
    for (int jl = 0; jl < 8; jl++)
#pragma unroll
        for (int mm = 0; mm < 4; mm++) acc[jl][mm] = 0ull;
#pragma unroll 4
    for (int k = 0; k < HH; k += 4) {
        ulonglong2 w0 = *(const ulonglong2*)&Ws[(tc +  0) * WS_STRIDE + k];
        ulonglong2 w1 = *(const ulonglong2*)&Ws[(tc + 32) * WS_STRIDE + k];
        ulonglong2 w2 = *(const ulonglong2*)&Ws[(tc + 64) * WS_STRIDE + k];
        ulonglong2 w3 = *(const ulonglong2*)&Ws[(tc + 96) * WS_STRIDE + k];
#pragma unroll
        for (int jl = 0; jl < 8; jl++) {
            ulonglong2 a = *(const ulonglong2*)&As[(jj0 + jl) * HH + k];
            fma2(acc[jl][0], a.x, w0.x); fma2(acc[jl][0], a.y, w0.y);
            fma2(acc[jl][1], a.x, w1.x); fma2(acc[jl][1], a.y, w1.y);
            fma2(acc[jl][2], a.x, w2.x); fma2(acc[jl][2], a.y, w2.y);
            fma2(acc[jl][3], a.x, w3.x); fma2(acc[jl][3], a.y, w3.y);
        }
    }
    float bv[4];
#pragma unroll
    for (int mm = 0; mm < 4; mm++) bv[mm] = bias[tc + 32 * mm];
    float* dst = g_lin + (size_t)m * ROWS_H * HH;
#pragma unroll
    for (int jl = 0; jl < 8; jl++) {
        size_t row = (size_t)(r0 + jj0 + jl) * HH;
#pragma unroll
        for (int mm = 0; mm < 4; mm++) {
            float2 p = unpack2(acc[jl][mm]);
            dst[row + tc + 32 * mm] = p.x + p.y + bv[mm];
        }
    }
}

// ---------------- K2: stats reduce (fp64) + h path + h_out ----------------
__device__ __forceinline__ double blk_red(double v, double* sb) {
    int tid = threadIdx.x;
    sb[tid] = v; __syncthreads();
    for (int o = 128; o > 0; o >>= 1) {
        if (tid < o) sb[tid] += sb[tid + o];
        __syncthreads();
    }
    double r = sb[0]; __syncthreads();
    return r;
}

__global__ void k_finalize(const float* __restrict__ h_in,
                           const float* __restrict__ gamma_h, const float* __restrict__ beta_h,
                           const float* __restrict__ gamma_e, const float* __restrict__ beta_e,
                           float* __restrict__ out_h) {
    __shared__ double sb[256];
    __shared__ float sbroad[2];
    int n = blockIdx.x;
    int tid = threadIdx.x;

    double s = 0.0, q = 0.0;
    for (int p = tid; p < NBLK2; p += 256) {
        s += (double)g_statS[(size_t)n * NBLK2 + p];
        q += (double)g_statQ[(size_t)n * NBLK2 + p];
    }
    s = blk_red(s, sb);
    q = blk_red(q, sb);
    if (tid == 0) {
        double mean = s / (double)ROWS_E;
        double var  = q / (double)ROWS_E - mean * mean;
        float rstd  = (float)(1.0 / sqrt(var + (double)EPS));
        float sc    = gamma_e[n] * rstd;
        g_scaleE[n] = sc;
        g_shiftE[n] = beta_e[n] - (float)mean * sc;
    }

    double hs = 0.0, hq = 0.0;
    for (int r = tid; r < ROWS_H; r += 256) {
        const float* ap = &g_aggp[(size_t)n * NBLK2 + r * 2];
        float agg = ap[0] + ap[1];
        float hn  = g_lin[(size_t)r * HH + n] + agg;  // Uh + agg
        g_hnew[(size_t)r * HH + n] = hn;
        hs += (double)hn; hq += (double)hn * (double)hn;
    }
    hs = blk_red(hs, sb);
    hq = blk_red(hq, sb);
    if (tid == 0) {
        double mean = hs / (double)ROWS_H;
        double var  = hq / (double)ROWS_H - mean * mean;
        float rstd  = (float)(1.0 / sqrt(var + (double)EPS));
        float sc    = gamma_h[n] * rstd;
        sbroad[0]   = sc;
        sbroad[1]   = beta_h[n] - (float)mean * sc;
    }
    __syncthreads();
    float sc = sbroad[0], sh = sbroad[1];
    for (int r = tid; r < ROWS_H; r += 256) {
        float v = fmaf(g_hnew[(size_t)r * HH + n], sc, sh);
        out_h[(size_t)r * HH + n] = h_in[(size_t)r * HH + n] + fmaxf(v, 0.f);
    }
}

// ---------------- K3: e epilogue ----------------
__global__ void k_epi(const float* __restrict__ e_in, float* __restrict__ out_e) {
    int tid = threadIdx.x;
    const float4* en4 = (const float4*)g_enew;
    const float4* ei4 = (const float4*)e_in;
    const float4* sc4 = (const float4*)g_scaleE;
    const float4* sh4 = (const float4*)g_shiftE;
    float4* out4 = (float4*)out_e;
#pragma unroll
    for (int it = 0; it < 4; it++) {
        size_t f = (size_t)blockIdx.x * 1024 + it * 256 + tid;
        int c = (int)(f & 31);
        float4 sc = __ldg(&sc4[c]);
        float4 sh = __ldg(&sh4[c]);
        float4 x  = en4[f];
        float4 ei = ei4[f];
        float4 o;
        o.x = ei.x + fmaxf(fmaf(x.x, sc.x, sh.x), 0.f);
        o.y = ei.y + fmaxf(fmaf(x.y, sc.y, sh.y), 0.f);
        o.z = ei.z + fmaxf(fmaf(x.z, sc.z, sh.z), 0.f);
        o.w = ei.w + fmaxf(fmaf(x.w, sc.w, sh.w), 0.f);
        out4[f] = o;
    }
}

extern "C" void kernel_launch(void* const* d_in, const int* in_sizes, int n_in,
                              void* d_out, int out_size) {
    (void)in_sizes; (void)n_in; (void)out_size;
    const float* h  = (const float*)d_in[0];
    const float* e  = (const float*)d_in[1];
    const float* Uw = (const float*)d_in[3];
    const float* Ub = (const float*)d_in[4];
    const float* Vw = (const float*)d_in[5];
    const float* Vb = (const float*)d_in[6];
    const float* Aw = (const float*)d_in[7];
    const float* Ab = (const float*)d_in[8];
    const float* Bw = (const float*)d_in[9];
    const float* Bb = (const float*)d_in[10];
    const float* Cw = (const float*)d_in[11];
    const float* Cb = (const float*)d_in[12];
    const float* gh = (const float*)d_in[13];
    const float* bh = (const float*)d_in[14];
    const float* ge = (const float*)d_in[15];
    const float* be = (const float*)d_in[16];
    float* out = (float*)d_out;   // [h_out (131072) | e_out (33554432)]

    cudaFuncSetAttribute(k_lin,  cudaFuncAttributeMaxDynamicSharedMemorySize, SMEM_LIN);
    cudaFuncSetAttribute(k_main, cudaFuncAttributeMaxDynamicSharedMemorySize, SM_TOTAL);

    k_lin<<<dim3(ROWS_H / 64, 5), 256, SMEM_LIN>>>(h, Uw, Ub, Vw, Vb, Aw, Ab, Bw, Bb, Cw);
    // MEASUREMENT ROUND: k_main launched twice (idempotent; pure function of its
    // inputs). Delta vs R15 total == k_main duration. Remove in next round.
    k_main<<<GRID_MAIN, 256, SM_TOTAL>>>(e, Cb);
    k_main<<<GRID_MAIN, 256, SM_TOTAL>>>(e, Cb);
    k_finalize<<<HH, 256>>>(h, gh, bh, ge, be, out);
    k_epi<<<ROWS_E * HH / 4096, 256>>>(e, out + ROWS_H * HH);
}

// round 17
// speedup vs baseline: 1.0001x; 1.0001x over previous
#include <cuda_runtime.h>
#include <cuda_fp16.h>
#include <cstdint>

// Problem constants
#define BB 4
#define VV 256
#define HH 128
constexpr int ROWS_H = BB * VV;           // 1024
constexpr int ROWS_E = BB * VV * VV;      // 262144
constexpr int NBLK2  = ROWS_E / 128;      // 2048 stat row-blocks (128 rows each)
constexpr int GRID_MAIN = ROWS_E / 256;   // 1024 (one block per (b,i))
constexpr float EPS  = 1e-5f;

// ---------------- smem geometry for k_main ----------------
constexpr int LDC    = 72;                  // fp16 elems per tile row (144 B; 9 units, odd)
constexpr int TILE_B = 128 * LDC * 2;       // 18432 B per fp16 tile (128 rows x 64 cols)
constexpr int SM_C2  = 0;                   // 128 floats
constexpr int SM_AHI = 1024;
constexpr int SM_BW0 = SM_AHI + TILE_B;     // 19456
constexpr int SM_BW1 = SM_BW0 + TILE_B;     // 37888
constexpr int SM_RED = SM_BW1 + TILE_B;     // 56320 (3 x 512 floats)
constexpr int SM_TOTAL = SM_RED + 6144;     // 62464 -> 2 CTAs/SM easily

// Scratch
__device__ float g_enew[(size_t)ROWS_E * HH];   // 134 MB
__device__ float g_lin[4 * ROWS_H * HH];        // Uh,Vh,Ah,Bh
__device__ __align__(16) char g_bt[2 * TILE_B]; // pre-converted Cw fp16 [chunk]
__device__ float g_statS[HH * NBLK2];
__device__ float g_statQ[HH * NBLK2];
__device__ float g_aggp[HH * NBLK2];
__device__ float g_hnew[ROWS_H * HH];
__device__ float g_scaleE[HH];
__device__ float g_shiftE[HH];

__device__ __forceinline__ uint32_t smem_u32(const void* p) {
    uint32_t a;
    asm("{ .reg .u64 t; cvta.to.shared.u64 t, %1; cvt.u32.u64 %0, t; }" : "=r"(a) : "l"(p));
    return a;
}
__device__ __forceinline__ void ldmatrix_x4(uint32_t& r0, uint32_t& r1, uint32_t& r2, uint32_t& r3, uint32_t addr) {
    asm volatile("ldmatrix.sync.aligned.m8n8.x4.shared.b16 {%0,%1,%2,%3}, [%4];"
        : "=r"(r0), "=r"(r1), "=r"(r2), "=r"(r3) : "r"(addr) : "memory");
}
__device__ __forceinline__ void mma16816(float (&d)[4], const uint32_t (&a)[4], uint32_t b0, uint32_t b1) {
    asm("mma.sync.aligned.m16n8k16.row.col.f32.f16.f16.f32 "
        "{%0,%1,%2,%3}, {%4,%5,%6,%7}, {%8,%9}, {%0,%1,%2,%3};"
        : "+f"(d[0]), "+f"(d[1]), "+f"(d[2]), "+f"(d[3])
        : "r"(a[0]), "r"(a[1]), "r"(a[2]), "r"(a[3]), "r"(b0), "r"(b1));
}
__device__ __forceinline__ void cp_async16(uint32_t smem_dst, const void* gmem_src) {
    asm volatile("cp.async.cg.shared.global [%0], [%1], 16;" :: "r"(smem_dst), "l"(gmem_src) : "memory");
}
#define CP_COMMIT() asm volatile("cp.async.commit_group;" ::: "memory")
#define CP_WAIT(n)  asm volatile("cp.async.wait_group %0;" :: "n"(n) : "memory")

__device__ __forceinline__ void cvt_store4(float4 v, char* smem, uint32_t off) {
    __half h0 = __float2half_rn(v.x), h1 = __float2half_rn(v.y);
    __half h2 = __float2half_rn(v.z), h3 = __float2half_rn(v.w);
    uint2 u;
    u.x = ((uint32_t)__half_as_ushort(h1) << 16) | __half_as_ushort(h0);
    u.y = ((uint32_t)__half_as_ushort(h3) << 16) | __half_as_ushort(h2);
    *(uint2*)(smem + off) = u;
}

// ---------------- K1: HMMA Ce GEMM (fp16, TM=256 per block) ----------------
__global__ void __launch_bounds__(256, 2)
k_main(const float* __restrict__ e, const float* __restrict__ Cb) {
    extern __shared__ char sm[];
    uint32_t smb = smem_u32(sm);
    int tid = threadIdx.x;
    int wid = tid >> 5, lane = tid & 31;

    int blk = blockIdx.x;         // == bi = b*V + i
    int b   = blk >> 8;
    size_t rbase0 = (size_t)blk * 256;

    // c2 = Cb + Bh[bi]
    if (tid < HH)
        ((float*)(sm + SM_C2))[tid] = Cb[tid] + g_lin[(size_t)3 * ROWS_H * HH + (size_t)blk * HH + tid];

    // Both B chunk tiles, once per block
    for (int i = tid; i < 2 * TILE_B / 16; i += 256)
        cp_async16(smb + SM_BW0 + i * 16, g_bt + i * 16);
    CP_COMMIT();

    int wm = wid >> 1, wn = wid & 1;     // 4 x 2 warp grid, warp tile 32x64
    uint32_t aLaneOff = (uint32_t)(wm * 32 + (lane & 15)) * (LDC * 2) + (lane >> 4) * 16;
    uint32_t bLaneOff = (uint32_t)(wn * 64 + (((lane >> 4) & 1) * 8) + (lane & 7)) * (LDC * 2)
                      + ((lane >> 3) & 1) * 16;

#pragma unroll
    for (int t = 0; t < 2; t++) {
        size_t rbase = rbase0 + t * 128;
        float d[2][8][4];
#pragma unroll
        for (int mt = 0; mt < 2; mt++)
#pragma unroll
            for (int nt = 0; nt < 8; nt++)
#pragma unroll
                for (int q = 0; q < 4; q++) d[mt][nt][q] = 0.f;

#pragma unroll
        for (int ch = 0; ch < 2; ch++) {
            // load + convert A (128 rows x 64 K) — direct LDG
            const float* eb = e + rbase * HH + ch * 64;
            for (int idx = tid; idx < 128 * 16; idx += 256) {
                int row = idx >> 4, c4 = idx & 15;
                uint32_t off = (uint32_t)row * (LDC * 2) + c4 * 8;
                float4 ev = *(const float4*)&eb[(size_t)row * HH + c4 * 4];
                cvt_store4(ev, sm, SM_AHI + off);
            }
            if (t == 0 && ch == 0) { CP_WAIT(0); }
            __syncthreads();

            uint32_t aBase = smb + SM_AHI + aLaneOff;
            uint32_t bBase = smb + (ch ? SM_BW1 : SM_BW0) + bLaneOff;
#pragma unroll
            for (int kk = 0; kk < 4; kk++) {
                uint32_t bb[16];
#pragma unroll
                for (int q = 0; q < 4; q++)
                    ldmatrix_x4(bb[q * 4], bb[q * 4 + 1], bb[q * 4 + 2], bb[q * 4 + 3],
                                bBase + kk * 32 + (uint32_t)q * 16 * (LDC * 2));
                uint32_t a0[4], a1[4];
                ldmatrix_x4(a0[0], a0[1], a0[2], a0[3], aBase + kk * 32);
                ldmatrix_x4(a1[0], a1[1], a1[2], a1[3], aBase + kk * 32 + 16 * (LDC * 2));
#pragma unroll
                for (int nt = 0; nt < 8; nt++) {
                    uint32_t b0 = bb[(nt >> 1) * 4 + (nt & 1) * 2];
                    uint32_t b1 = bb[(nt >> 1) * 4 + (nt & 1) * 2 + 1];
                    mma16816(d[0][nt], a0, b0, b1);
                    mma16816(d[1][nt], a1, b0, b1);
                }
            }
            __syncthreads();   // A tile consumed; next chunk may overwrite
        }

        // -------- fragment-direct epilogue for this tile --------
        {
            int g = lane >> 2, t2 = (lane & 3) * 2;
            const float* c2s = (const float*)(sm + SM_C2);
            const float* ahB = g_lin + (size_t)2 * ROWS_H * HH + (size_t)(b * VV + t * 128) * HH;
            const float* vhB = g_lin + (size_t)1 * ROWS_H * HH + (size_t)(b * VV + t * 128) * HH;
            float* enB = g_enew + rbase * HH;
            float* redS = (float*)(sm + SM_RED);
            float* redQ = redS + 512;
            float* redA = redQ + 512;

#pragma unroll
            for (int nt = 0; nt < 8; nt++) {
                int c = wn * 64 + nt * 8 + t2;
                float c2a = c2s[c], c2b = c2s[c + 1];
                float pS0 = 0.f, pS1 = 0.f, pQ0 = 0.f, pQ1 = 0.f, pA0 = 0.f, pA1 = 0.f;
#pragma unroll
                for (int mt = 0; mt < 2; mt++) {
#pragma unroll
                    for (int h = 0; h < 2; h++) {
                        int r = wm * 32 + mt * 16 + h * 8 + g;
                        float2 ahv = *(const float2*)&ahB[(size_t)r * HH + c];
                        float2 vhv = *(const float2*)&vhB[(size_t)r * HH + c];
                        float x0 = d[mt][nt][h * 2 + 0] + c2a + ahv.x;
                        float x1 = d[mt][nt][h * 2 + 1] + c2b + ahv.y;
                        *(float2*)&enB[(size_t)r * HH + c] = make_float2(x0, x1);
                        pS0 += x0; pS1 += x1;
                        pQ0 = fmaf(x0, x0, pQ0); pQ1 = fmaf(x1, x1, pQ1);
                        pA0 = fmaf(vhv.x, 1.f / (1.f + __expf(-x0)), pA0);
                        pA1 = fmaf(vhv.y, 1.f / (1.f + __expf(-x1)), pA1);
                    }
                }
#pragma unroll
                for (int m = 4; m <= 16; m <<= 1) {
                    pS0 += __shfl_xor_sync(0xffffffffu, pS0, m);
                    pS1 += __shfl_xor_sync(0xffffffffu, pS1, m);
                    pQ0 += __shfl_xor_sync(0xffffffffu, pQ0, m);
                    pQ1 += __shfl_xor_sync(0xffffffffu, pQ1, m);
                    pA0 += __shfl_xor_sync(0xffffffffu, pA0, m);
                    pA1 += __shfl_xor_sync(0xffffffffu, pA1, m);
                }
                if (g == 0) {
                    redS[wm * 128 + c] = pS0; redS[wm * 128 + c + 1] = pS1;
                    redQ[wm * 128 + c] = pQ0; redQ[wm * 128 + c + 1] = pQ1;
                    redA[wm * 128 + c] = pA0; redA[wm * 128 + c + 1] = pA1;
                }
            }
        }
        __syncthreads();
        if (tid < HH) {
            float* redS = (float*)(sm + SM_RED);
            float* redQ = redS + 512;
            float* redA = redQ + 512;
            float S = 0.f, Q = 0.f, A = 0.f;
#pragma unroll
            for (int w = 0; w < 4; w++) {
                S += redS[w * 128 + tid];
                Q += redQ[w * 128 + tid];
                A += redA[w * 128 + tid];
            }
            int rowblk = blk * 2 + t;
            g_statS[(size_t)tid * NBLK2 + rowblk] = S;
            g_statQ[(size_t)tid * NBLK2 + rowblk] = Q;
            g_aggp[(size_t)tid * NBLK2 + rowblk]  = A;
        }
        // red not rewritten until after ≥2 barriers in next tile's MMA phases — safe
    }
}

// ---------------- K0: four small linears + Cw pre-convert (y==4) ----------------
constexpr int WS_STRIDE = 132;
constexpr int SMEM_LIN = (HH * WS_STRIDE + 64 * HH) * 4;

__device__ __forceinline__ void fma2(unsigned long long& d, unsigned long long a, unsigned long long b) {
    asm("fma.rn.f32x2 %0, %1, %2, %0;" : "+l"(d) : "l"(a), "l"(b));
}
__device__ __forceinline__ float2 unpack2(unsigned long long v) {
    float2 r; asm("mov.b64 {%0,%1}, %2;" : "=f"(r.x), "=f"(r.y) : "l"(v)); return r;
}

__global__ void k_lin(const float* __restrict__ h,
                      const float* __restrict__ W0, const float* __restrict__ b0,
                      const float* __restrict__ W1, const float* __restrict__ b1,
                      const float* __restrict__ W2, const float* __restrict__ b2,
                      const float* __restrict__ W3, const float* __restrict__ b3,
                      const float* __restrict__ Cw) {
    if (blockIdx.y == 4) {
        int ch = blockIdx.x & 1;
        if (blockIdx.x >= 2) return;
        char* dst = g_bt + (size_t)ch * TILE_B;
        const float* wb = Cw + ch * 64;
        for (int idx = threadIdx.x; idx < 128 * 16; idx += 256) {
            int row = idx >> 4, c4 = idx & 15;
            uint32_t off = (uint32_t)row * (LDC * 2) + c4 * 8;
            float4 wv = *(const float4*)&wb[(size_t)row * HH + c4 * 4];
            cvt_store4(wv, dst, off);
        }
        return;
    }
    extern __shared__ float smf[];
    float* Ws = smf;
    float* As = Ws + HH * WS_STRIDE;

    int m = blockIdx.y;
    const float* W    = (m == 0) ? W0 : (m == 1) ? W1 : (m == 2) ? W2 : W3;
    const float* bias = (m == 0) ? b0 : (m == 1) ? b1 : (m == 2) ? b2 : b3;

    int tid = threadIdx.x;
    for (int i = tid; i < HH * 32; i += 256) {
        int n = i >> 5, kc = i & 31;
        *(float4*)&Ws[n * WS_STRIDE + kc * 4] = *(const float4*)&W[n * HH + kc * 4];
    }
    int r0 = blockIdx.x * 64;
    const float4* hsrc = (const float4*)(h + (size_t)r0 * HH);
    for (int i = tid; i < 64 * 32; i += 256) ((float4*)As)[i] = hsrc[i];
    __syncthreads();

    int tr = tid >> 5, tc = tid & 31;
    int jj0 = tr * 8;
    unsigned long long acc[8][4];
#pragma unroll
    for (int jl = 0; jl < 8; jl++)
#pragma unroll
        for (int mm = 0; mm < 4; mm++) acc[jl][mm] = 0ull;
#pragma unroll 4
    for (int k = 0; k < HH; k += 4) {
        ulonglong2 w0 = *(const ulonglong2*)&Ws[(tc +  0) * WS_STRIDE + k];
        ulonglong2 w1 = *(const ulonglong2*)&Ws[(tc + 32) * WS_STRIDE + k];
        ulonglong2 w2 = *(const ulonglong2*)&Ws[(tc + 64) * WS_STRIDE + k];
        ulonglong2 w3 = *(const ulonglong2*)&Ws[(tc + 96) * WS_STRIDE + k];
#pragma unroll
        for (int jl = 0; jl < 8; jl++) {
            ulonglong2 a = *(const ulonglong2*)&As[(jj0 + jl) * HH + k];
            fma2(acc[jl][0], a.x, w0.x); fma2(acc[jl][0], a.y, w0.y);
            fma2(acc[jl][1], a.x, w1.x); fma2(acc[jl][1], a.y, w1.y);
            fma2(acc[jl][2], a.x, w2.x); fma2(acc[jl][2], a.y, w2.y);
            fma2(acc[jl][3], a.x, w3.x); fma2(acc[jl][3], a.y, w3.y);
        }
    }
    float bv[4];
#pragma unroll
    for (int mm = 0; mm < 4; mm++) bv[mm] = bias[tc + 32 * mm];
    float* dst = g_lin + (size_t)m * ROWS_H * HH;
#pragma unroll
    for (int jl = 0; jl < 8; jl++) {
        size_t row = (size_t)(r0 + jj0 + jl) * HH;
#pragma unroll
        for (int mm = 0; mm < 4; mm++) {
            float2 p = unpack2(acc[jl][mm]);
            dst[row + tc + 32 * mm] = p.x + p.y + bv[mm];
        }
    }
}

// ---------------- K2: stats reduce (fp64) + h path + h_out ----------------
__device__ __forceinline__ double blk_red(double v, double* sb) {
    int tid = threadIdx.x;
    sb[tid] = v; __syncthreads();
    for (int o = 128; o > 0; o >>= 1) {
        if (tid < o) sb[tid] += sb[tid + o];
        __syncthreads();
    }
    double r = sb[0]; __syncthreads();
    return r;
}

__global__ void k_finalize(const float* __restrict__ h_in,
                           const float* __restrict__ gamma_h, const float* __restrict__ beta_h,
                           const float* __restrict__ gamma_e, const float* __restrict__ beta_e,
                           float* __restrict__ out_h) {
    __shared__ double sb[256];
    __shared__ float sbroad[2];
    int n = blockIdx.x;
    int tid = threadIdx.x;

    double s = 0.0, q = 0.0;
    for (int p = tid; p < NBLK2; p += 256) {
        s += (double)g_statS[(size_t)n * NBLK2 + p];
        q += (double)g_statQ[(size_t)n * NBLK2 + p];
    }
    s = blk_red(s, sb);
    q = blk_red(q, sb);
    if (tid == 0) {
        double mean = s / (double)ROWS_E;
        double var  = q / (double)ROWS_E - mean * mean;
        float rstd  = (float)(1.0 / sqrt(var + (double)EPS));
        float sc    = gamma_e[n] * rstd;
        g_scaleE[n] = sc;
        g_shiftE[n] = beta_e[n] - (float)mean * sc;
    }

    double hs = 0.0, hq = 0.0;
    for (int r = tid; r < ROWS_H; r += 256) {
        const float* ap = &g_aggp[(size_t)n * NBLK2 + r * 2];
        float agg = ap[0] + ap[1];
        float hn  = g_lin[(size_t)r * HH + n] + agg;  // Uh + agg
        g_hnew[(size_t)r * HH + n] = hn;
        hs += (double)hn; hq += (double)hn * (double)hn;
    }
    hs = blk_red(hs, sb);
    hq = blk_red(hq, sb);
    if (tid == 0) {
        double mean = hs / (double)ROWS_H;
        double var  = hq / (double)ROWS_H - mean * mean;
        float rstd  = (float)(1.0 / sqrt(var + (double)EPS));
        float sc    = gamma_h[n] * rstd;
        sbroad[0]   = sc;
        sbroad[1]   = beta_h[n] - (float)mean * sc;
    }
    __syncthreads();
    float sc = sbroad[0], sh = sbroad[1];
    for (int r = tid; r < ROWS_H; r += 256) {
        float v = fmaf(g_hnew[(size_t)r * HH + n], sc, sh);
        out_h[(size_t)r * HH + n] = h_in[(size_t)r * HH + n] + fmaxf(v, 0.f);
    }
}

// ---------------- K3: e epilogue ----------------
__global__ void k_epi(const float* __restrict__ e_in, float* __restrict__ out_e) {
    int tid = threadIdx.x;
    const float4* en4 = (const float4*)g_enew;
    const float4* ei4 = (const float4*)e_in;
    const float4* sc4 = (const float4*)g_scaleE;
    const float4* sh4 = (const float4*)g_shiftE;
    float4* out4 = (float4*)out_e;
#pragma unroll
    for (int it = 0; it < 4; it++) {
        size_t f = (size_t)blockIdx.x * 1024 + it * 256 + tid;
        int c = (int)(f & 31);
        float4 sc = __ldg(&sc4[c]);
        float4 sh = __ldg(&sh4[c]);
        float4 x  = en4[f];
        float4 ei = ei4[f];
        float4 o;
        o.x = ei.x + fmaxf(fmaf(x.x, sc.x, sh.x), 0.f);
        o.y = ei.y + fmaxf(fmaf(x.y, sc.y, sh.y), 0.f);
        o.z = ei.z + fmaxf(fmaf(x.z, sc.z, sh.z), 0.f);
        o.w = ei.w + fmaxf(fmaf(x.w, sc.w, sh.w), 0.f);
        out4[f] = o;
    }
}

extern "C" void kernel_launch(void* const* d_in, const int* in_sizes, int n_in,
                              void* d_out, int out_size) {
    (void)in_sizes; (void)n_in; (void)out_size;
    const float* h  = (const float*)d_in[0];
    const float* e  = (const float*)d_in[1];
    const float* Uw = (const float*)d_in[3];
    const float* Ub = (const float*)d_in[4];
    const float* Vw = (const float*)d_in[5];
    const float* Vb = (const float*)d_in[6];
    const float* Aw = (const float*)d_in[7];
    const float* Ab = (const float*)d_in[8];
    const float* Bw = (const float*)d_in[9];
    const float* Bb = (const float*)d_in[10];
    const float* Cw = (const float*)d_in[11];
    const float* Cb = (const float*)d_in[12];
    const float* gh = (const float*)d_in[13];
    const float* bh = (const float*)d_in[14];
    const float* ge = (const float*)d_in[15];
    const float* be = (const float*)d_in[16];
    float* out = (float*)d_out;   // [h_out (131072) | e_out (33554432)]

    cudaFuncSetAttribute(k_lin,  cudaFuncAttributeMaxDynamicSharedMemorySize, SMEM_LIN);
    cudaFuncSetAttribute(k_main, cudaFuncAttributeMaxDynamicSharedMemorySize, SM_TOTAL);

    k_lin<<<dim3(ROWS_H / 64, 5), 256, SMEM_LIN>>>(h, Uw, Ub, Vw, Vb, Aw, Ab, Bw, Bb, Cw);
    // MEASUREMENT ROUND: k_main launched twice (idempotent; pure function of its
    // inputs). Delta vs R15 total == k_main duration. Remove in next round.
    k_main<<<GRID_MAIN, 256, SM_TOTAL>>>(e, Cb);
    k_main<<<GRID_MAIN, 256, SM_TOTAL>>>(e, Cb);
    k_finalize<<<HH, 256>>>(h, gh, bh, ge, be, out);
    k_epi<<<ROWS_E * HH / 4096, 256>>>(e, out + ROWS_H * HH);
}